// round 14
// baseline (speedup 1.0000x reference)
#include <cuda_runtime.h>
#include <cuda_bf16.h>
#include <cstdint>

// Problem constants
#define BB 4
#define LL 1024
#define HH 8
#define DD 512
#define DK 64
#define HB 32           // H*B
#define ML 4096         // B*L
#define LOG2E 1.4426950408889634f

// Scratch (allocation-free rule: __device__ globals).
__device__ __align__(16) float g_QP[ML * DD];
__device__ __align__(16) float g_KP[ML * DD];
__device__ __align__(16) float g_VP[ML * DD];
__device__ __align__(16) float g_OH[ML * DD];

// ---------------------------------------------------------------------------
// Warp-level bf16 MMA (baseline PTX, sm_80+; compiles for compute_103).
// D(16x8, f32) += A(16x16, bf16 row) * B(16x8, bf16 col)
// ---------------------------------------------------------------------------
__device__ __forceinline__ void mma16816(float d[4], const uint32_t a[4],
                                         const uint32_t b[2]) {
    asm volatile(
        "mma.sync.aligned.m16n8k16.row.col.f32.bf16.bf16.f32 "
        "{%0,%1,%2,%3}, {%4,%5,%6,%7}, {%8,%9}, {%0,%1,%2,%3};"
        : "+f"(d[0]), "+f"(d[1]), "+f"(d[2]), "+f"(d[3])
        : "r"(a[0]), "r"(a[1]), "r"(a[2]), "r"(a[3]), "r"(b[0]), "r"(b[1]));
}

// Smem tile pitch: 40 halves (80 B) -> bank stride 20 mod 32; the 8 quad
// rows of a fragment load hit banks {0,20,8,28,16,4,24,12}+0..3 = all 32
// distinct -> conflict-free LDS.32. All accesses 4B-aligned (even half cols).
#define TP 40

__device__ __forceinline__ uint16_t bf16_bits(float x) {
    __nv_bfloat16 h = __float2bfloat16(x);
    return __bfloat16_as_ushort(h);
}

// ---------------------------------------------------------------------------
// Staging: fp32 global -> bf16 hi/lo tiles.
// NT (K-major rows): tile[r][k] = g[(row0+r)*ld + col0+k], 32 k per chunk.
// ---------------------------------------------------------------------------
__device__ __forceinline__ void stage_nt(const float* __restrict__ g, int ld,
                                         int row0, int col0, int nrows,
                                         uint16_t* __restrict__ hi,
                                         uint16_t* __restrict__ lo) {
    for (int idx = threadIdx.x; idx < nrows * 8; idx += 256) {
        int r  = idx >> 3;
        int c4 = (idx & 7) << 2;
        float4 v = *(const float4*)&g[(size_t)(row0 + r) * ld + col0 + c4];
        float xs[4] = {v.x, v.y, v.z, v.w};
        uint16_t hb[4], lb[4];
#pragma unroll
        for (int u = 0; u < 4; u++) {
            __nv_bfloat16 h = __float2bfloat16(xs[u]);
            hb[u] = __bfloat16_as_ushort(h);
            lb[u] = bf16_bits(xs[u] - __bfloat162float(h));
        }
        int base = r * TP + c4;
        *(uint32_t*)&hi[base]     = (uint32_t)hb[0] | ((uint32_t)hb[1] << 16);
        *(uint32_t*)&hi[base + 2] = (uint32_t)hb[2] | ((uint32_t)hb[3] << 16);
        *(uint32_t*)&lo[base]     = (uint32_t)lb[0] | ((uint32_t)lb[1] << 16);
        *(uint32_t*)&lo[base + 2] = (uint32_t)lb[2] | ((uint32_t)lb[3] << 16);
    }
}

// NN (transpose during staging): tile[n][k] = g[(k0+k)*ld + col0+n]
template <int BN>
__device__ __forceinline__ void stage_nn(const float* __restrict__ g, int ld,
                                         int k0, int col0,
                                         uint16_t* __restrict__ hi,
                                         uint16_t* __restrict__ lo) {
    for (int idx = threadIdx.x; idx < 32 * (BN / 4); idx += 256) {
        int k  = idx / (BN / 4);
        int n4 = (idx % (BN / 4)) * 4;
        float4 v = *(const float4*)&g[(size_t)(k0 + k) * ld + col0 + n4];
        float xs[4] = {v.x, v.y, v.z, v.w};
#pragma unroll
        for (int u = 0; u < 4; u++) {
            __nv_bfloat16 h = __float2bfloat16(xs[u]);
            hi[(n4 + u) * TP + k] = __bfloat16_as_ushort(h);
            lo[(n4 + u) * TP + k] = bf16_bits(xs[u] - __bfloat162float(h));
        }
    }
}

// ---------------------------------------------------------------------------
// Tensor-core GEMM body (mma.sync). BM=128, BK=32 bf16/chunk, 256 thr, 8 warps
// (4m x 2n); warp tile 32 x (BN/2). Split: x = hi+lo bf16; products
// hi*hi + hi*lo + lo*hi accumulate in fp32 (err ~2^-16).
//   BT=true : B global [N][K] K-major (NT);  BT=false: B global [K][N] (NN)
// ---------------------------------------------------------------------------
template <int BN, bool BT>
__device__ __forceinline__ void mma_gemm_body(
    const float* __restrict__ A, int lda,
    const float* __restrict__ Bm, int ldb,
    float* __restrict__ C, int ldc, int K, float alpha)
{
    constexpr int NT = BN / 16;   // n8 tiles per warp
    __shared__ uint16_t sAh[128 * TP], sAl[128 * TP];
    __shared__ uint16_t sBh[BN * TP], sBl[BN * TP];

    const int tid  = threadIdx.x;
    const int lane = tid & 31;
    const int wid  = tid >> 5;
    const int wm   = wid >> 1;          // 0..3
    const int wn   = wid & 1;           // 0..1
    const int m0   = blockIdx.y * 128;
    const int n0   = blockIdx.x * BN;
    const int r4   = lane >> 2;         // 0..7
    const int c2   = (lane & 3) * 2;    // 0,2,4,6

    float acc[2][NT][4];
#pragma unroll
    for (int mt = 0; mt < 2; mt++)
#pragma unroll
        for (int nt = 0; nt < NT; nt++)
#pragma unroll
            for (int u = 0; u < 4; u++) acc[mt][nt][u] = 0.0f;

    const int nch = K >> 5;
    for (int s = 0; s < nch; s++) {
        const int k0 = s << 5;
        stage_nt(A, lda, m0, k0, 128, sAh, sAl);
        if (BT) stage_nt(Bm, ldb, n0, k0, BN, sBh, sBl);
        else    stage_nn<BN>(Bm, ldb, k0, n0, sBh, sBl);
        __syncthreads();

#pragma unroll
        for (int k16 = 0; k16 < 2; k16++) {
            const int kc = k16 * 16;
            uint32_t a_h[2][4], a_l[2][4], bfr[NT][2];
#pragma unroll
            for (int mt = 0; mt < 2; mt++) {
                int rb = (wm * 32 + mt * 16 + r4) * TP + kc + c2;
                a_h[mt][0] = *(const uint32_t*)&sAh[rb];
                a_h[mt][1] = *(const uint32_t*)&sAh[rb + 8 * TP];
                a_h[mt][2] = *(const uint32_t*)&sAh[rb + 8];
                a_h[mt][3] = *(const uint32_t*)&sAh[rb + 8 * TP + 8];
                a_l[mt][0] = *(const uint32_t*)&sAl[rb];
                a_l[mt][1] = *(const uint32_t*)&sAl[rb + 8 * TP];
                a_l[mt][2] = *(const uint32_t*)&sAl[rb + 8];
                a_l[mt][3] = *(const uint32_t*)&sAl[rb + 8 * TP + 8];
            }
            // B_hi: products hi*hi and lo*hi
#pragma unroll
            for (int nt = 0; nt < NT; nt++) {
                int nb = (wn * (BN / 2) + nt * 8 + r4) * TP + kc + c2;
                bfr[nt][0] = *(const uint32_t*)&sBh[nb];
                bfr[nt][1] = *(const uint32_t*)&sBh[nb + 8];
            }
#pragma unroll
            for (int mt = 0; mt < 2; mt++)
#pragma unroll
                for (int nt = 0; nt < NT; nt++) {
                    mma16816(acc[mt][nt], a_h[mt], bfr[nt]);
                    mma16816(acc[mt][nt], a_l[mt], bfr[nt]);
                }
            // B_lo: product hi*lo
#pragma unroll
            for (int nt = 0; nt < NT; nt++) {
                int nb = (wn * (BN / 2) + nt * 8 + r4) * TP + kc + c2;
                bfr[nt][0] = *(const uint32_t*)&sBl[nb];
                bfr[nt][1] = *(const uint32_t*)&sBl[nb + 8];
            }
#pragma unroll
            for (int mt = 0; mt < 2; mt++)
#pragma unroll
                for (int nt = 0; nt < NT; nt++)
                    mma16816(acc[mt][nt], a_h[mt], bfr[nt]);
        }
        __syncthreads();
    }

    // Epilogue: fragment-direct float2 stores (quads cover 32B segments).
#pragma unroll
    for (int mt = 0; mt < 2; mt++) {
        int row = m0 + wm * 32 + mt * 16 + r4;
#pragma unroll
        for (int nt = 0; nt < NT; nt++) {
            int col = n0 + wn * (BN / 2) + nt * 8 + c2;
            float2 o0 = make_float2(acc[mt][nt][0] * alpha,
                                    acc[mt][nt][1] * alpha);
            float2 o1 = make_float2(acc[mt][nt][2] * alpha,
                                    acc[mt][nt][3] * alpha);
            *(float2*)&C[(size_t)row * ldc + col]       = o0;
            *(float2*)&C[(size_t)(row + 8) * ldc + col] = o1;
        }
    }
}

// ---------------------------------------------------------------------------
// GEMM wrappers
// ---------------------------------------------------------------------------
__global__ void __launch_bounds__(256, 1)
proj_mma(const float* __restrict__ Q, const float* __restrict__ K_,
         const float* __restrict__ V, const float* __restrict__ Wq,
         const float* __restrict__ Wk, const float* __restrict__ Wv)
{
    const float* A; const float* W; float* C;
    if (blockIdx.z == 0)      { A = Q;  W = Wq; C = g_QP; }
    else if (blockIdx.z == 1) { A = K_; W = Wk; C = g_KP; }
    else                      { A = V;  W = Wv; C = g_VP; }
    mma_gemm_body<128, true>(A, DD, W, DD, C, DD, DD, 1.0f);
}

__global__ void __launch_bounds__(256, 1)
scores_mma(float* __restrict__ series)
{
    int z = blockIdx.z, h = z >> 2, b = z & 3;
    const float* A  = g_QP + (size_t)b * LL * DD + h * DK;
    const float* Bm = g_KP + (size_t)b * LL * DD + h * DK;
    float* C = series + (size_t)z * LL * LL;
    mma_gemm_body<128, true>(A, DD, Bm, DD, C, LL, DK, 0.125f);
}

__global__ void __launch_bounds__(256, 1)
pv_mma(const float* __restrict__ series)
{
    int z = blockIdx.z, h = z >> 2, b = z & 3;
    const float* A  = series + (size_t)z * LL * LL;
    const float* Bm = g_VP + (size_t)b * LL * DD + h * DK;
    float* C = g_OH + (size_t)b * LL * DD + h * DK;
    mma_gemm_body<64, false>(A, LL, Bm, DD, C, DD, LL, 1.0f);
}

__global__ void __launch_bounds__(256, 1)
outp_mma(const float* __restrict__ Wo, float* __restrict__ out)
{
    mma_gemm_body<128, true>(g_OH, DD, Wo, DD, out, DD, DD, 1.0f);
}

// ---------------------------------------------------------------------------
// Block reductions (256 threads = 8 warps) for prior/softmax.
// ---------------------------------------------------------------------------
template <int OP>  // 0 = sum, 1 = max
__device__ __forceinline__ float block_reduce(float v)
{
    __shared__ float red[8];
#pragma unroll
    for (int o = 16; o > 0; o >>= 1) {
        float w = __shfl_xor_sync(0xffffffffu, v, o);
        v = (OP == 1) ? fmaxf(v, w) : (v + w);
    }
    int lane = threadIdx.x & 31;
    int wrp  = threadIdx.x >> 5;
    if (lane == 0) red[wrp] = v;
    __syncthreads();
    float r = red[0];
#pragma unroll
    for (int i = 1; i < 8; i++) r = (OP == 1) ? fmaxf(r, red[i]) : (r + red[i]);
    return r;
}

// ---------------------------------------------------------------------------
// Prior (unchanged from the 498us passing kernel).
// ---------------------------------------------------------------------------
__global__ void prior_kernel(const float* __restrict__ Sigma,
                             const float* __restrict__ Wsig,
                             float* __restrict__ prior)
{
    int r  = blockIdx.x;
    int i  = r & (LL - 1);
    int hb = r >> 10;
    int h  = hb >> 2;
    int b  = hb & 3;

    float sig = 0.0f;
#pragma unroll
    for (int k = 0; k < HH; k++)
        sig = fmaf(Sigma[((size_t)(b * LL + i)) * HH + k], Wsig[h * HH + k], sig);

    float t = -LOG2E / (2.0f * sig * sig);

    int j0 = threadIdx.x * 4;
    float v[4];
    float s = 0.0f;
#pragma unroll
    for (int u = 0; u < 4; u++) {
        float d = (float)(i - (j0 + u));
        v[u] = exp2f(d * d * t);
        s += v[u];
    }
    float tot = block_reduce<0>(s);
    float inv = 1.0f / tot;
    float4 o = make_float4(v[0] * inv, v[1] * inv, v[2] * inv, v[3] * inv);
    *(float4*)&prior[(size_t)r * LL + j0] = o;
}

// ---------------------------------------------------------------------------
// Softmax in-place (unchanged).
// ---------------------------------------------------------------------------
__global__ void softmax_kernel(float* __restrict__ series)
{
    size_t base = (size_t)blockIdx.x * LL;
    int j0 = threadIdx.x * 4;
    float4 sv = *(const float4*)&series[base + j0];
    float s[4] = {sv.x, sv.y, sv.z, sv.w};

    float mx = fmaxf(fmaxf(s[0], s[1]), fmaxf(s[2], s[3]));
    mx = block_reduce<1>(mx);

    float e[4];
    float sum = 0.0f;
#pragma unroll
    for (int u = 0; u < 4; u++) {
        e[u] = exp2f((s[u] - mx) * LOG2E);
        sum += e[u];
    }
    __syncthreads();
    sum = block_reduce<0>(sum);
    float inv = 1.0f / sum;
    float4 o = make_float4(e[0] * inv, e[1] * inv, e[2] * inv, e[3] * inv);
    *(float4*)&series[base + j0] = o;
}

// ---------------------------------------------------------------------------
// Launch.  d_out: prior[32M] | series[32M] | out[2M] floats
// ---------------------------------------------------------------------------
extern "C" void kernel_launch(void* const* d_in, const int* in_sizes, int n_in,
                              void* d_out, int out_size)
{
    const float* Sigma = (const float*)d_in[0];
    const float* Q     = (const float*)d_in[1];
    const float* K     = (const float*)d_in[2];
    const float* V     = (const float*)d_in[3];
    const float* Wsig  = (const float*)d_in[4];
    const float* Wq    = (const float*)d_in[5];
    const float* Wk    = (const float*)d_in[6];
    const float* Wv    = (const float*)d_in[7];
    const float* Wo    = (const float*)d_in[8];

    float* prior  = (float*)d_out;
    float* series = prior + (size_t)HB * LL * LL;
    float* obuf   = series + (size_t)HB * LL * LL;

    // Prior path (independent)
    prior_kernel<<<HB * LL, 256>>>(Sigma, Wsig, prior);

    // Projections
    proj_mma<<<dim3(DD / 128, ML / 128, 3), 256>>>(Q, K, V, Wq, Wk, Wv);

    // Attention
    scores_mma<<<dim3(LL / 128, LL / 128, HB), 256>>>(series);
    softmax_kernel<<<HB * LL, 256>>>(series);
    pv_mma<<<dim3(1, LL / 128, HB), 256>>>(series);

    // Output projection
    outp_mma<<<dim3(DD / 128, ML / 128, 1), 256>>>(Wo, obuf);
}